// round 14
// baseline (speedup 1.0000x reference)
#include <cuda_runtime.h>
#include <cstdint>
#include <math.h>

#define NF 64
#define Bn 5000
#define Ln 10
#define Tn 25
#define Kn 8
#define NMAX 1000000

typedef unsigned long long ull;

// u-table [t][b][l][k] (40 MB): gather rows contiguous 32B.
__device__ float g_u[(size_t)Tn * Bn * Ln * Kn];
// Per-row random effect, gathered while u is L2-resident (32 MB).
__device__ float g_r[(size_t)NMAX * Kn];

// ---------------------------------------------------------------------------
// Kernel 1: chol (parallel) + AR(1) scan with smem-staged eps (R13 proven).
// ---------------------------------------------------------------------------
#define CHB 128
#define CH_F4 50
#define CH_STRIDE_F4 51
#define PRE_SMEM (CHB * CH_STRIDE_F4 * 16)

__global__ void __launch_bounds__(256, 2)
pre_kernel(const float* __restrict__ eps, const float* __restrict__ raw_rho,
           const float* __restrict__ Sigma) {
    extern __shared__ float4 se[];
    __shared__ float sL[Kn][Ln * Ln];
    __shared__ float4 sd4[Ln][2];

    int tid = threadIdx.x;

    for (int i = tid; i < Kn * Ln * Ln; i += 256)
        ((float*)sL)[i] = Sigma[i];
    __syncthreads();

    int mk = tid / Ln;
    int mi = tid % Ln;
    bool act = tid < Kn * Ln;
#pragma unroll
    for (int j = 0; j < Ln; j++) {
        if (act && mi == j) {
            float s = sL[mk][j * Ln + j];
            for (int p = 0; p < j; p++) {
                float v = sL[mk][j * Ln + p];
                s -= v * v;
            }
            sL[mk][j * Ln + j] = sqrtf(s);
        }
        __syncthreads();
        if (act && mi > j) {
            float s = sL[mk][mi * Ln + j];
            for (int p = 0; p < j; p++)
                s -= sL[mk][mi * Ln + p] * sL[mk][j * Ln + p];
            sL[mk][mi * Ln + j] = __fdividef(s, sL[mk][j * Ln + j]);
        }
        __syncthreads();
    }
    if (act) ((float*)sd4)[mi * Kn + mk] = sL[mk][mi * Ln + mi];

    const int baseCh = blockIdx.x * CHB;
    const float4* eg = (const float4*)eps;
    const long gbase = (long)baseCh * CH_F4;
    const long gmax  = (long)Bn * Ln * CH_F4;
#pragma unroll
    for (int k = 0; k < CHB * CH_F4 / 256; k++) {
        int i = tid + k * 256;
        int c = i / CH_F4;
        int pos = i - c * CH_F4;
        float4 v = make_float4(0.f, 0.f, 0.f, 0.f);
        if (gbase + i < gmax) v = __ldcs(&eg[gbase + i]);
        se[c * CH_STRIDE_F4 + pos] = v;
    }
    __syncthreads();

    int c = tid >> 1;
    int q = tid & 1;
    int chain = baseCh + c;
    if (chain >= Bn * Ln) return;
    int l = chain % Ln;

    float4 rr = *(const float4*)(raw_rho + l * Kn + q * 4);
    float4 rho = make_float4(tanhf(rr.x), tanhf(rr.y), tanhf(rr.z), tanhf(rr.w));
    float4 d = sd4[l][q];

    const float4* ech = se + c * CH_STRIDE_F4;
    float4* ug = (float4*)g_u;
    const int ustride = Bn * Ln * Kn / 4;
    int uidx = chain * 2 + q;

    float4 u = ech[q];
    ug[uidx] = u;
#pragma unroll
    for (int t = 1; t < Tn; t++) {
        float4 ev = ech[t * 2 + q];
        u.x = fmaf(rho.x, u.x, d.x * ev.x);
        u.y = fmaf(rho.y, u.y, d.y * ev.y);
        u.z = fmaf(rho.z, u.z, d.z * ev.z);
        u.w = fmaf(rho.w, u.w, d.w * ev.w);
        ug[t * ustride + uidx] = u;
    }
}

// ---------------------------------------------------------------------------
// Kernel 1b: gather while u is L2-resident. g_r[n,:] = u[off[n],:].
// ids reads + g_r writes coalesced; u reads hit L2 (just written by pre).
// ---------------------------------------------------------------------------
__global__ void __launch_bounds__(256)
gather_kernel(const int* __restrict__ batter_ids,
              const int* __restrict__ league_ids,
              const int* __restrict__ season_ids, int N) {
    int n = blockIdx.x * 256 + threadIdx.x;
    if (n >= N) return;
    int off = ((season_ids[n] * Bn + batter_ids[n]) * Ln +
               league_ids[n]) * Kn;
    const float4* up = (const float4*)(g_u + off);
    float4 u0 = up[0];
    float4 u1 = up[1];
    float4* gp = (float4*)g_r + (size_t)n * 2;
    __stcs(&gp[0], u0);
    __stcs(&gp[1], u1);
}

// ---------------------------------------------------------------------------
// Kernel 2 (persistent, cp.async double-buffer, thread-per-row):
//   out[n,:] = X[n,:] @ beta + g_r[n,:]
// All accesses are now streams: X via cp.async, g_r register-prefetched
// one tile ahead (coalesced), out via __stcs. No random DRAM.
// ---------------------------------------------------------------------------
#define FMA2(d_, a_, b_, c_) \
    asm("fma.rn.f32x2 %0, %1, %2, %3;" : "=l"(d_) : "l"(a_), "l"(b_), "l"(c_))
#define CP_ASYNC16(dst, src) \
    asm volatile("cp.async.cg.shared.global [%0], [%1], 16;" \
                 :: "r"(dst), "l"(src))
#define CP_COMMIT() asm volatile("cp.async.commit_group;")
#define CP_WAIT(n)  asm volatile("cp.async.wait_group %0;" :: "n"(n))

__device__ __forceinline__ ull dupf(float x) {
    unsigned int w = __float_as_uint(x);
    ull q;
    asm("mov.b64 %0, {%1,%2};" : "=l"(q) : "r"(w), "r"(w));
    return q;
}

__device__ __forceinline__ float4 lds128(unsigned int a) {
    float4 v;
    asm volatile("ld.shared.v4.f32 {%0,%1,%2,%3}, [%4];"
                 : "=f"(v.x), "=f"(v.y), "=f"(v.z), "=f"(v.w) : "r"(a));
    return v;
}

#define THREADS 128
#define STAGE_ROWS 128
#define STAGE_BYTES 32768
#define NSTAGE 2
#define SMEM_MAIN (NSTAGE * STAGE_BYTES + 2048)

__global__ void __launch_bounds__(THREADS, 3)
main_kernel(const float* __restrict__ X,
            const float* __restrict__ beta,
            float* __restrict__ out, int N) {
    extern __shared__ char smem[];
    unsigned int sbase;
    asm("{ .reg .u64 t0; cvta.to.shared.u64 t0, %1; cvt.u32.u64 %0, t0; }"
        : "=r"(sbase) : "l"(smem));
    unsigned int bbase = sbase + NSTAGE * STAGE_BYTES;

    int tid = threadIdx.x;

    // beta -> smem
    {
        const ulonglong2* bg = (const ulonglong2*)beta;
        *((ulonglong2*)(smem + NSTAGE * STAGE_BYTES) + tid) = bg[tid];
    }

    int T = (N + STAGE_ROWS - 1) / STAGE_ROWS;
    int GRID = gridDim.x;
    const float4* gr4 = (const float4*)g_r;

    auto issue_stage = [&](int slot, int ti) {
        unsigned int stb = sbase + slot * STAGE_BYTES;
#pragma unroll
        for (int j = 0; j < 16; j++) {
            int idx = tid + j * THREADS;
            int rl  = idx >> 4;
            int c   = idx & 15;
            int gn  = ti * STAGE_ROWS + rl;
            if (gn > N - 1) gn = N - 1;
            const float* src = X + (size_t)gn * NF + c * 4;
            unsigned int dst = stb + rl * 256 + ((c ^ (rl & 7)) << 4);
            CP_ASYNC16(dst, src);
        }
    };

    // ---- prologue: tile0 into slot0; g_r for tile0 ----
    {
        int t0 = blockIdx.x;
        if (t0 < T) issue_stage(0, t0);
        CP_COMMIT();
    }
    float4 rA0, rA1;
    {
        int n0 = min(blockIdx.x * STAGE_ROWS + tid, N - 1);
        rA0 = __ldcs(&gr4[(size_t)n0 * 2]);
        rA1 = __ldcs(&gr4[(size_t)n0 * 2 + 1]);
    }
    __syncthreads();    // beta visible

    for (int i = 0; ; i++) {
        int ti = blockIdx.x + i * GRID;
        if (ti >= T) break;
        int slot = i & 1;

        if (i > 0) __syncthreads();
        int tif = blockIdx.x + (i + 1) * GRID;
        if (tif < T) issue_stage(slot ^ 1, tif);
        CP_COMMIT();

        // prefetch g_r for next tile (coalesced stream)
        float4 rB0, rB1;
        {
            int tin = min(blockIdx.x + (i + 1) * GRID, T - 1);
            int nn = min(tin * STAGE_ROWS + tid, N - 1);
            rB0 = __ldcs(&gr4[(size_t)nn * 2]);
            rB1 = __ldcs(&gr4[(size_t)nn * 2 + 1]);
        }

        CP_WAIT(1);
        __syncthreads();

        unsigned int rb = sbase + slot * STAGE_BYTES + tid * 256;
        int rsw = tid & 7;
        ull a0 = 0, a1 = 0, a2 = 0, a3 = 0;
#pragma unroll
        for (int cc = 0; cc < 16; cc++) {
            float4 xv = lds128(rb + ((cc ^ rsw) << 4));
            float xs[4] = {xv.x, xv.y, xv.z, xv.w};
#pragma unroll
            for (int r = 0; r < 4; r++) {
                int j = cc * 4 + r;
                ull q = dupf(xs[r]);
                unsigned int ba = bbase + j * 32;
                ull b0, b1, b2, b3;
                asm volatile("ld.shared.v2.u64 {%0,%1}, [%2];"
                             : "=l"(b0), "=l"(b1) : "r"(ba));
                asm volatile("ld.shared.v2.u64 {%0,%1}, [%2];"
                             : "=l"(b2), "=l"(b3) : "r"(ba + 16));
                FMA2(a0, q, b0, a0);
                FMA2(a1, q, b1, a1);
                FMA2(a2, q, b2, a2);
                FMA2(a3, q, b3, a3);
            }
        }

        int n = ti * STAGE_ROWS + tid;
        if (n < N) {
            float f0, f1, f2, f3, f4, f5, f6, f7;
            asm("mov.b64 {%0,%1}, %2;" : "=f"(f0), "=f"(f1) : "l"(a0));
            asm("mov.b64 {%0,%1}, %2;" : "=f"(f2), "=f"(f3) : "l"(a1));
            asm("mov.b64 {%0,%1}, %2;" : "=f"(f4), "=f"(f5) : "l"(a2));
            asm("mov.b64 {%0,%1}, %2;" : "=f"(f6), "=f"(f7) : "l"(a3));
            float4 o0 = make_float4(f0 + rA0.x, f1 + rA0.y,
                                    f2 + rA0.z, f3 + rA0.w);
            float4 o1 = make_float4(f4 + rA1.x, f5 + rA1.y,
                                    f6 + rA1.z, f7 + rA1.w);
            float4* op = (float4*)(out + (size_t)n * Kn);
            __stcs(&op[0], o0);
            __stcs(&op[1], o1);
        }
        rA0 = rB0;
        rA1 = rB1;
    }
    CP_WAIT(0);
}

// ---------------------------------------------------------------------------
extern "C" void kernel_launch(void* const* d_in, const int* in_sizes, int n_in,
                              void* d_out, int out_size) {
    const float* X       = (const float*)d_in[0];
    const int*   bid     = (const int*)d_in[1];
    const int*   lid     = (const int*)d_in[2];
    const int*   sid     = (const int*)d_in[3];
    const float* beta    = (const float*)d_in[4];
    const float* raw_rho = (const float*)d_in[5];
    const float* Sigma   = (const float*)d_in[6];
    const float* eps     = (const float*)d_in[7];
    float*       out     = (float*)d_out;

    const int N = in_sizes[1];

    static int smem_set = 0;
    if (!smem_set) {
        cudaFuncSetAttribute(main_kernel,
                             cudaFuncAttributeMaxDynamicSharedMemorySize,
                             SMEM_MAIN);
        cudaFuncSetAttribute(pre_kernel,
                             cudaFuncAttributeMaxDynamicSharedMemorySize,
                             PRE_SMEM);
        smem_set = 1;
    }

    int preBlocks = (Bn * Ln + CHB - 1) / CHB;     // 391
    pre_kernel<<<preBlocks, 256, PRE_SMEM>>>(eps, raw_rho, Sigma);

    gather_kernel<<<(N + 255) / 256, 256>>>(bid, lid, sid, N);

    main_kernel<<<444, THREADS, SMEM_MAIN>>>(X, beta, out, N);
}